// round 15
// baseline (speedup 1.0000x reference)
#include <cuda_runtime.h>
#include <math.h>
#include <cstdint>

// ---------------------------------------------------------------------------
// casConv2d: B=1, C=128, H=W=32, OC=128, K=3, pad=1 -> OH=OW=32, L=1024
// 36 real chunks of 32 ckk-terms; front-pad chunk exactly zero after quant.
//
// NOTE: harness PTX target is compute_103 (no 'a') -> tcgen05 unavailable.
// Using Ampere-style mma.sync m16n8k8 tf32 (sm_80 baseline) with 3xTF32
// splits for fp32-grade accuracy.
//
// K0: w,x -> tf32 (hi, lo) pairs.
// K1m: per (oh-group, chunk j): D[l,oc] = sum_k X[l,k] W[oc,k] via mma.sync,
//      3 products (hh, hl, lh) accumulated fp32 -> g_part[l][j][oc].
// K2: block-per-l reduce/quant (R13 version, unchanged).
// ---------------------------------------------------------------------------

typedef unsigned long long u64;

__device__ float    g_part[1024u * 36u * 128u];   // [l][j][oc]
__device__ uint32_t w2g[2u * 147456u];            // [s][j][oc][m] tf32 bits
__device__ uint32_t x2g[2u * 131072u];            // [s][c][h][w]  tf32 bits

// ---- f32x2 helpers (K2) ----
__device__ __forceinline__ u64 fma2(u64 a, u64 b, u64 c) {
    u64 d;
    asm("fma.rn.f32x2 %0, %1, %2, %3;" : "=l"(d) : "l"(a), "l"(b), "l"(c));
    return d;
}
__device__ __forceinline__ u64 add2(u64 a, u64 b) {
    u64 d;
    asm("add.rn.f32x2 %0, %1, %2;" : "=l"(d) : "l"(a), "l"(b));
    return d;
}
__device__ __forceinline__ u64 bcast2(float v) {
    u64 d; unsigned u = __float_as_uint(v);
    asm("mov.b64 %0, {%1, %1};" : "=l"(d) : "r"(u));
    return d;
}
__device__ __forceinline__ float2 unpack2(u64 v) {
    float2 f;
    asm("mov.b64 {%0, %1}, %2;" : "=f"(f.x), "=f"(f.y) : "l"(v));
    return f;
}
__device__ __forceinline__ u64 pack2(float x, float y) {
    u64 d;
    asm("mov.b64 %0, {%1, %2};" : "=l"(d) : "f"(x), "f"(y));
    return d;
}

// ---- tf32 helpers ----
__device__ __forceinline__ uint32_t f2tf32(float v) {
    uint32_t r;
    asm("cvt.rna.tf32.f32 %0, %1;" : "=r"(r) : "f"(v));
    return r;
}
__device__ __forceinline__ void mma_tf32(float* d, const uint32_t* a,
                                         const uint32_t* b) {
    asm volatile(
        "mma.sync.aligned.m16n8k8.row.col.f32.tf32.tf32.f32 "
        "{%0,%1,%2,%3}, {%4,%5,%6,%7}, {%8,%9}, {%0,%1,%2,%3};"
        : "+f"(d[0]), "+f"(d[1]), "+f"(d[2]), "+f"(d[3])
        : "r"(a[0]), "r"(a[1]), "r"(a[2]), "r"(a[3]), "r"(b[0]), "r"(b[1]));
}

// ---------------------------------------------------------------------------
// K0: tf32 hi/lo splits.  w2g[s][j][oc][m], x2g[s][c*1024+h*32+w].
// ---------------------------------------------------------------------------
__global__ void k_split(const float* __restrict__ x, const float* __restrict__ w) {
    int i = blockIdx.x * 256 + threadIdx.x;
    if (i < 147456) {
        float v = w[i];
        uint32_t hi = f2tf32(v);
        uint32_t lo = f2tf32(v - __uint_as_float(hi));
        int oc = i / 1152;
        int r  = i - oc * 1152;
        int j  = r >> 5;
        int m  = r & 31;
        int dst = (j << 12) + (oc << 5) + m;
        w2g[dst]          = hi;
        w2g[147456 + dst] = lo;
    }
    if (i < 131072) {
        float v = x[i];
        uint32_t hi = f2tf32(v);
        uint32_t lo = f2tf32(v - __uint_as_float(hi));
        x2g[i]          = hi;
        x2g[131072 + i] = lo;
    }
}

// ---------------------------------------------------------------------------
// K1m: grid (4 oh-groups, 36 chunks), 256 threads (8 warps).
// Warp wid owns oc range [wid*16, wid*16+16) (2 n-tiles of 8).
// Loop it=0..7: oh = bx*8+it. Per oh: build x_s im2col (32l x 32k, 2 splits),
// then per mt(2 l-tiles of 16) x k(4) x nt(2): 3 mma -> acc -> g_part.
// Smem stride 36: (4*row+col) mod 32 distinct -> all LDS conflict-free.
// ---------------------------------------------------------------------------
__global__ void __launch_bounds__(256)
k_partials_mma() {
    __shared__ uint32_t w_s[2][128][36];
    __shared__ uint32_t x_s[2][32][36];

    const int tid  = threadIdx.x;
    const int lane = tid & 31;
    const int wid  = tid >> 5;
    const int j    = blockIdx.y;
    const int oh0  = blockIdx.x * 8;

    // fill w_s: 2 x 128 x 32 u32 = 2048 uint4 loads
    for (int e = tid; e < 2048; e += 256) {
        int s   = e >> 10;
        int rem = e & 1023;
        int oc  = rem >> 3;
        int q   = rem & 7;
        uint4 v = *(const uint4*)(w2g + s * 147456 + (j << 12) + (oc << 5) + (q << 2));
        w_s[s][oc][q * 4 + 0] = v.x;
        w_s[s][oc][q * 4 + 1] = v.y;
        w_s[s][oc][q * 4 + 2] = v.z;
        w_s[s][oc][q * 4 + 3] = v.w;
    }

    // per-lane im2col constants: m = lane
    const int idx = (j << 5) + lane;
    const int c   = idx / 9;
    const int rm  = idx - c * 9;
    const int kh  = rm / 3;
    const int kw  = rm - kh * 3;

    __syncthreads();

    // preload W fragments: B[s][nt][k][2]
    uint32_t B[2][2][4][2];
    const int bn = (wid << 4) + (lane >> 2);
    const int bk = lane & 3;
#pragma unroll
    for (int s = 0; s < 2; ++s)
#pragma unroll
        for (int nt = 0; nt < 2; ++nt)
#pragma unroll
            for (int k = 0; k < 4; ++k) {
                B[s][nt][k][0] = w_s[s][bn + nt * 8][k * 8 + bk];
                B[s][nt][k][1] = w_s[s][bn + nt * 8][k * 8 + bk + 4];
            }

    const int ar = lane >> 2;
    const int ac = lane & 3;

    for (int it = 0; it < 8; ++it) {
        const int oh = oh0 + it;

        // build x_s: warp wid fills rows l = wid*4..+3, lane = m (conflict-free)
        {
            const int gh  = oh - 1 + kh;
            const bool hok = (unsigned)gh < 32u;
            const int xb  = (c << 10) + (gh << 5);
#pragma unroll
            for (int s = 0; s < 2; ++s)
#pragma unroll
                for (int i = 0; i < 4; ++i) {
                    const int l  = (wid << 2) + i;
                    const int gw = l - 1 + kw;
                    uint32_t v = 0u;
                    if (hok && (unsigned)gw < 32u)
                        v = x2g[s * 131072 + xb + gw];
                    x_s[s][l][lane] = v;
                }
        }
        __syncthreads();

#pragma unroll
        for (int mt = 0; mt < 2; ++mt) {
            float acc[2][4] = {};
#pragma unroll
            for (int k = 0; k < 4; ++k) {
                uint32_t ah[4], al[4];
                const int r0 = mt * 16 + ar;
                const int c0 = k * 8 + ac;
                ah[0] = x_s[0][r0][c0];
                ah[1] = x_s[0][r0 + 8][c0];
                ah[2] = x_s[0][r0][c0 + 4];
                ah[3] = x_s[0][r0 + 8][c0 + 4];
                al[0] = x_s[1][r0][c0];
                al[1] = x_s[1][r0 + 8][c0];
                al[2] = x_s[1][r0][c0 + 4];
                al[3] = x_s[1][r0 + 8][c0 + 4];
#pragma unroll
                for (int nt = 0; nt < 2; ++nt) {
                    mma_tf32(acc[nt], ah, B[0][nt][k]);   // xhi * whi
                    mma_tf32(acc[nt], ah, B[1][nt][k]);   // xhi * wlo
                    mma_tf32(acc[nt], al, B[0][nt][k]);   // xlo * whi
                }
            }
            // store: l = oh*32 + mt*16 + ar (+8), oc = wid*16 + nt*8 + 2*ac (+1)
            const int lA = (oh << 5) + mt * 16 + ar;
#pragma unroll
            for (int nt = 0; nt < 2; ++nt) {
                const int oc0 = (wid << 4) + nt * 8 + (ac << 1);
                float* p0 = g_part + (size_t)lA * 4608 + (j << 7) + oc0;
                float* p1 = g_part + (size_t)(lA + 8) * 4608 + (j << 7) + oc0;
                *(float2*)p0 = make_float2(acc[nt][0], acc[nt][1]);
                *(float2*)p1 = make_float2(acc[nt][2], acc[nt][3]);
            }
        }
        __syncthreads();   // x_s rewritten next it
    }
}

// ---------------------------------------------------------------------------
// K2: block (128 thr, 4 warps) per l; grid = 1024. (R13 version, unchanged)
// ---------------------------------------------------------------------------
__global__ void __launch_bounds__(128)
k_quant(const float* __restrict__ bias, float* __restrict__ out) {
    const int tid  = threadIdx.x;
    const int lane = tid & 31;
    const int wid  = tid >> 5;
    const int l    = blockIdx.x;
    const int j0   = wid * 9;

    const longlong2* bp =
        (const longlong2*)(g_part + (size_t)l * 4608) + lane;

    __shared__ longlong2 s[4][32];

    longlong2 pv[9];
    u64 t0 = 0ull, t1 = 0ull;
#pragma unroll
    for (int j = 0; j < 9; ++j) {
        pv[j] = bp[(j0 + j) * 32];
        t0 = add2(t0, (u64)pv[j].x);
        t1 = add2(t1, (u64)pv[j].y);
    }
    s[wid][lane] = make_longlong2((long long)t0, (long long)t1);
    __syncthreads();

    longlong2 bb = ((const longlong2*)bias)[lane];
    u64 tot0 = (u64)bb.x, tot1 = (u64)bb.y;
#pragma unroll
    for (int w2 = 0; w2 < 4; ++w2) {
        longlong2 v = s[w2][lane];
        tot0 = add2(tot0, (u64)v.x);
        tot1 = add2(tot1, (u64)v.y);
    }
    float2 f0 = unpack2(tot0), f1 = unpack2(tot1);
    float mx = fmaxf(fmaxf(f0.x, f0.y), fmaxf(f1.x, f1.y));
    float mn = fminf(fminf(f0.x, f0.y), fminf(f1.x, f1.y));
#pragma unroll
    for (int sft = 16; sft > 0; sft >>= 1) {
        mx = fmaxf(mx, __shfl_xor_sync(0xffffffffu, mx, sft));
        mn = fminf(mn, __shfl_xor_sync(0xffffffffu, mn, sft));
    }

    const float sc = (mx - mn) * (1.0f / 255.0f);
    float z = -mn / sc;                              // inf/nan if sc==0
    z = fminf(fmaxf(z, 0.0f), 255.0f);               // clip (nan -> 0)
    if (isnan(z)) z = 0.0f;
    const float zp  = truncf(z);                     // .int() truncation
    const float rcp = 1.0f / sc;

    const float MAGIC = 12582912.0f;                 // 1.5 * 2^23
    const u64 rcp2 = bcast2(rcp);
    const u64 mg2  = bcast2(MAGIC);
    const u64 zm2  = bcast2(zp - MAGIC);

    float ox = 0.f, oy = 0.f, oz = 0.f, ow = 0.f;
#pragma unroll
    for (int j = 0; j < 9; ++j) {
        u64 r0 = add2(fma2((u64)pv[j].x, rcp2, mg2), zm2);  // rint(v/sc)+zp
        u64 r1 = add2(fma2((u64)pv[j].y, rcp2, mg2), zm2);
        float2 c0 = unpack2(r0), c1 = unpack2(r1);
        ox += fminf(fmaxf(c0.x, 0.0f), 255.0f);
        oy += fminf(fmaxf(c0.y, 0.0f), 255.0f);
        oz += fminf(fmaxf(c1.x, 0.0f), 255.0f);
        ow += fminf(fmaxf(c1.y, 0.0f), 255.0f);
    }
    __syncthreads();
    s[wid][lane] = make_longlong2((long long)pack2(ox, oy),
                                  (long long)pack2(oz, ow));
    __syncthreads();

    const float* sf = (const float*)s;               // [warp][128 oc]
    float v = sf[tid] + sf[128 + tid] + sf[256 + tid] + sf[384 + tid];
    out[(tid << 10) + l] = (v - 36.0f * zp) * sc;
}

// ---------------------------------------------------------------------------
extern "C" void kernel_launch(void* const* d_in, const int* in_sizes, int n_in,
                              void* d_out, int out_size) {
    const float *x = nullptr, *w = nullptr, *b = nullptr;
    for (int i = 0; i < n_in; ++i) {
        if      (in_sizes[i] == 131072) x = (const float*)d_in[i];  // 128*32*32
        else if (in_sizes[i] == 147456) w = (const float*)d_in[i];  // 128*128*9
        else if (in_sizes[i] == 128)    b = (const float*)d_in[i];
    }
    k_split<<<576, 256>>>(x, w);
    k_partials_mma<<<dim3(4, 36), 256>>>();
    k_quant<<<1024, 128>>>(b, (float*)d_out);
}

// round 16
// speedup vs baseline: 1.0801x; 1.0801x over previous
#include <cuda_runtime.h>
#include <math.h>
#include <cstdint>

// ---------------------------------------------------------------------------
// casConv2d: B=1, C=128, H=W=32, OC=128, K=3, pad=1 -> OH=OW=32, L=1024
// 36 real chunks of 32 ckk-terms; front-pad chunk exactly zero after quant.
//
// compute_103 target (no 'a'): tcgen05 unavailable -> Ampere mma.sync
// m16n8k8 tf32, 3 split-products (hh, hl, lh) for fp32-grade accuracy.
//
// K1m: grid (32 oh, 36 chunks) = 1152 blocks, 256 thr, ONE oh per block.
//   f32 -> tf32 hi/lo conversion inline during smem fill (no split kernel).
//   Per block: fill w_s (16KB f32 -> 2 splits) + x_s (im2col) -> 1 sync ->
//   48 mma/warp -> g_part[l][j][oc].
// K2: block-per-l reduce/quant (R13 version, unchanged).
// ---------------------------------------------------------------------------

typedef unsigned long long u64;

__device__ float g_part[1024u * 36u * 128u];   // [l][j][oc]

// ---- f32x2 helpers (K2) ----
__device__ __forceinline__ u64 fma2(u64 a, u64 b, u64 c) {
    u64 d;
    asm("fma.rn.f32x2 %0, %1, %2, %3;" : "=l"(d) : "l"(a), "l"(b), "l"(c));
    return d;
}
__device__ __forceinline__ u64 add2(u64 a, u64 b) {
    u64 d;
    asm("add.rn.f32x2 %0, %1, %2;" : "=l"(d) : "l"(a), "l"(b));
    return d;
}
__device__ __forceinline__ u64 bcast2(float v) {
    u64 d; unsigned u = __float_as_uint(v);
    asm("mov.b64 %0, {%1, %1};" : "=l"(d) : "r"(u));
    return d;
}
__device__ __forceinline__ float2 unpack2(u64 v) {
    float2 f;
    asm("mov.b64 {%0, %1}, %2;" : "=f"(f.x), "=f"(f.y) : "l"(v));
    return f;
}
__device__ __forceinline__ u64 pack2(float x, float y) {
    u64 d;
    asm("mov.b64 %0, {%1, %2};" : "=l"(d) : "f"(x), "f"(y));
    return d;
}

// ---- tf32 helpers ----
__device__ __forceinline__ uint32_t f2tf32(float v) {
    uint32_t r;
    asm("cvt.rna.tf32.f32 %0, %1;" : "=r"(r) : "f"(v));
    return r;
}
__device__ __forceinline__ void mma_tf32(float* d, const uint32_t* a,
                                         const uint32_t* b) {
    asm volatile(
        "mma.sync.aligned.m16n8k8.row.col.f32.tf32.tf32.f32 "
        "{%0,%1,%2,%3}, {%4,%5,%6,%7}, {%8,%9}, {%0,%1,%2,%3};"
        : "+f"(d[0]), "+f"(d[1]), "+f"(d[2]), "+f"(d[3])
        : "r"(a[0]), "r"(a[1]), "r"(a[2]), "r"(a[3]), "r"(b[0]), "r"(b[1]));
}

// ---------------------------------------------------------------------------
// K1m: grid (32, 36), 256 threads (8 warps), one oh per block.
// Warp wid owns oc [wid*16, wid*16+16) (2 n-tiles of 8).
// Smem stride 36: (4*row+col) mod 32 distinct -> all LDS conflict-free.
// ---------------------------------------------------------------------------
__global__ void __launch_bounds__(256)
k_partials_mma(const float* __restrict__ x, const float* __restrict__ w) {
    __shared__ uint32_t w_s[2][128][36];
    __shared__ uint32_t x_s[2][32][36];

    const int tid  = threadIdx.x;
    const int lane = tid & 31;
    const int wid  = tid >> 5;
    const int oh   = blockIdx.x;
    const int j    = blockIdx.y;
    const int base = j << 5;

    // fill w_s with inline tf32 split: 4096 floats = 1024 float4, 4/thread
#pragma unroll
    for (int k = 0; k < 4; ++k) {
        int e  = tid + (k << 8);
        int oc = e >> 3;
        int q  = e & 7;                       // m = 4q .. 4q+3
        float4 v = *(const float4*)(w + oc * 1152 + base + (q << 2));
        float vv[4] = {v.x, v.y, v.z, v.w};
#pragma unroll
        for (int i = 0; i < 4; ++i) {
            uint32_t hi = f2tf32(vv[i]);
            uint32_t lo = f2tf32(vv[i] - __uint_as_float(hi));
            w_s[0][oc][(q << 2) + i] = hi;
            w_s[1][oc][(q << 2) + i] = lo;
        }
    }

    // fill x_s (im2col, inline split): lane = m; warp wid fills l = wid*4..+3
    {
        const int idx = base + lane;
        const int c   = idx / 9;
        const int rm  = idx - c * 9;
        const int kh  = rm / 3;
        const int kw  = rm - kh * 3;
        const int gh  = oh - 1 + kh;
        const bool hok = (unsigned)gh < 32u;
        const int xb  = (c << 10) + (gh << 5);
#pragma unroll
        for (int i = 0; i < 4; ++i) {
            const int l  = (wid << 2) + i;
            const int gw = l - 1 + kw;
            float v = 0.0f;
            if (hok && (unsigned)gw < 32u) v = x[xb + gw];
            uint32_t hi = f2tf32(v);
            uint32_t lo = f2tf32(v - __uint_as_float(hi));
            x_s[0][l][lane] = hi;
            x_s[1][l][lane] = lo;
        }
    }
    __syncthreads();

    // preload W fragments: B[s][nt][k][2]
    uint32_t B[2][2][4][2];
    const int bn = (wid << 4) + (lane >> 2);
    const int bk = lane & 3;
#pragma unroll
    for (int s = 0; s < 2; ++s)
#pragma unroll
        for (int nt = 0; nt < 2; ++nt)
#pragma unroll
            for (int k = 0; k < 4; ++k) {
                B[s][nt][k][0] = w_s[s][bn + nt * 8][k * 8 + bk];
                B[s][nt][k][1] = w_s[s][bn + nt * 8][k * 8 + bk + 4];
            }

    const int ar = lane >> 2;
    const int ac = lane & 3;

#pragma unroll
    for (int mt = 0; mt < 2; ++mt) {
        float acc[2][4] = {};
#pragma unroll
        for (int k = 0; k < 4; ++k) {
            uint32_t ah[4], al[4];
            const int r0 = mt * 16 + ar;
            const int c0 = k * 8 + ac;
            ah[0] = x_s[0][r0][c0];
            ah[1] = x_s[0][r0 + 8][c0];
            ah[2] = x_s[0][r0][c0 + 4];
            ah[3] = x_s[0][r0 + 8][c0 + 4];
            al[0] = x_s[1][r0][c0];
            al[1] = x_s[1][r0 + 8][c0];
            al[2] = x_s[1][r0][c0 + 4];
            al[3] = x_s[1][r0 + 8][c0 + 4];
#pragma unroll
            for (int nt = 0; nt < 2; ++nt) {
                mma_tf32(acc[nt], ah, B[0][nt][k]);   // xhi * whi
                mma_tf32(acc[nt], ah, B[1][nt][k]);   // xhi * wlo
                mma_tf32(acc[nt], al, B[0][nt][k]);   // xlo * whi
            }
        }
        // store: l = oh*32 + mt*16 + ar (+8), oc = wid*16 + nt*8 + 2*ac (+1)
        const int lA = (oh << 5) + mt * 16 + ar;
#pragma unroll
        for (int nt = 0; nt < 2; ++nt) {
            const int oc0 = (wid << 4) + nt * 8 + (ac << 1);
            float* p0 = g_part + (size_t)lA * 4608 + (j << 7) + oc0;
            float* p1 = g_part + (size_t)(lA + 8) * 4608 + (j << 7) + oc0;
            *(float2*)p0 = make_float2(acc[nt][0], acc[nt][1]);
            *(float2*)p1 = make_float2(acc[nt][2], acc[nt][3]);
        }
    }
}

// ---------------------------------------------------------------------------
// K2: block (128 thr, 4 warps) per l; grid = 1024. (R13 version, unchanged)
// ---------------------------------------------------------------------------
__global__ void __launch_bounds__(128)
k_quant(const float* __restrict__ bias, float* __restrict__ out) {
    const int tid  = threadIdx.x;
    const int lane = tid & 31;
    const int wid  = tid >> 5;
    const int l    = blockIdx.x;
    const int j0   = wid * 9;

    const longlong2* bp =
        (const longlong2*)(g_part + (size_t)l * 4608) + lane;

    __shared__ longlong2 s[4][32];

    longlong2 pv[9];
    u64 t0 = 0ull, t1 = 0ull;
#pragma unroll
    for (int j = 0; j < 9; ++j) {
        pv[j] = bp[(j0 + j) * 32];
        t0 = add2(t0, (u64)pv[j].x);
        t1 = add2(t1, (u64)pv[j].y);
    }
    s[wid][lane] = make_longlong2((long long)t0, (long long)t1);
    __syncthreads();

    longlong2 bb = ((const longlong2*)bias)[lane];
    u64 tot0 = (u64)bb.x, tot1 = (u64)bb.y;
#pragma unroll
    for (int w2 = 0; w2 < 4; ++w2) {
        longlong2 v = s[w2][lane];
        tot0 = add2(tot0, (u64)v.x);
        tot1 = add2(tot1, (u64)v.y);
    }
    float2 f0 = unpack2(tot0), f1 = unpack2(tot1);
    float mx = fmaxf(fmaxf(f0.x, f0.y), fmaxf(f1.x, f1.y));
    float mn = fminf(fminf(f0.x, f0.y), fminf(f1.x, f1.y));
#pragma unroll
    for (int sft = 16; sft > 0; sft >>= 1) {
        mx = fmaxf(mx, __shfl_xor_sync(0xffffffffu, mx, sft));
        mn = fminf(mn, __shfl_xor_sync(0xffffffffu, mn, sft));
    }

    const float sc = (mx - mn) * (1.0f / 255.0f);
    float z = -mn / sc;                              // inf/nan if sc==0
    z = fminf(fmaxf(z, 0.0f), 255.0f);               // clip (nan -> 0)
    if (isnan(z)) z = 0.0f;
    const float zp  = truncf(z);                     // .int() truncation
    const float rcp = 1.0f / sc;

    const float MAGIC = 12582912.0f;                 // 1.5 * 2^23
    const u64 rcp2 = bcast2(rcp);
    const u64 mg2  = bcast2(MAGIC);
    const u64 zm2  = bcast2(zp - MAGIC);

    float ox = 0.f, oy = 0.f, oz = 0.f, ow = 0.f;
#pragma unroll
    for (int j = 0; j < 9; ++j) {
        u64 r0 = add2(fma2((u64)pv[j].x, rcp2, mg2), zm2);  // rint(v/sc)+zp
        u64 r1 = add2(fma2((u64)pv[j].y, rcp2, mg2), zm2);
        float2 c0 = unpack2(r0), c1 = unpack2(r1);
        ox += fminf(fmaxf(c0.x, 0.0f), 255.0f);
        oy += fminf(fmaxf(c0.y, 0.0f), 255.0f);
        oz += fminf(fmaxf(c1.x, 0.0f), 255.0f);
        ow += fminf(fmaxf(c1.y, 0.0f), 255.0f);
    }
    __syncthreads();
    s[wid][lane] = make_longlong2((long long)pack2(ox, oy),
                                  (long long)pack2(oz, ow));
    __syncthreads();

    const float* sf = (const float*)s;               // [warp][128 oc]
    float v = sf[tid] + sf[128 + tid] + sf[256 + tid] + sf[384 + tid];
    out[(tid << 10) + l] = (v - 36.0f * zp) * sc;
}

// ---------------------------------------------------------------------------
extern "C" void kernel_launch(void* const* d_in, const int* in_sizes, int n_in,
                              void* d_out, int out_size) {
    const float *x = nullptr, *w = nullptr, *b = nullptr;
    for (int i = 0; i < n_in; ++i) {
        if      (in_sizes[i] == 131072) x = (const float*)d_in[i];  // 128*32*32
        else if (in_sizes[i] == 147456) w = (const float*)d_in[i];  // 128*128*9
        else if (in_sizes[i] == 128)    b = (const float*)d_in[i];
    }
    k_partials_mma<<<dim3(32, 36), 256>>>(x, w);
    k_quant<<<1024, 128>>>(b, (float*)d_out);
}